// round 11
// baseline (speedup 1.0000x reference)
#include <cuda_runtime.h>

#define BATCH 4
#define DD 32
#define HH 192
#define WW 192
#define DHW 1179648
#define NCH 7
#define NIDS 16
#define NB 32768                     // bucketing error <= 1/NB (provable)
#define CH 2048
#define NCHUNK (NB / CH)             // 16
#define BUCKW (2.0f / (float)NB)
#define VPB 512                      // voxels per k_main block
#define AVPB 2048                    // voxels per k_agg block

// Scratch (static device globals; no allocation anywhere)
__device__ unsigned g_hp[BATCH][NIDS][NB];   // pos hist, id-major (gt is scattered anyway)
__device__ unsigned g_hn[BATCH][NB][NIDS];   // neg hist, id-MINOR: 16 ids contiguous per bucket
__device__ unsigned long long g_chunk[BATCH][NIDS][NCHUNK];
__device__ unsigned long long g_choff[BATCH][NIDS][NCHUNK];
__device__ float g_agg[BATCH][NIDS][10];   // cnt, sx,sy,sz, s0,s1,s2, q0,q1,q2
__device__ float g_params[BATCH][NIDS][8]; // cx,cy,cz, e0,e1,e2, P, exists
__device__ float g_misc[BATCH][4];         // bg_seed, seed_l, var_sum, denom
__device__ float g_instl[BATCH];

__device__ __forceinline__ float blockReduceSum(float v, float* sh) {
    #pragma unroll
    for (int o = 16; o; o >>= 1) v += __shfl_down_sync(0xffffffffu, v, o);
    int lane = threadIdx.x & 31, w = threadIdx.x >> 5;
    if (lane == 0) sh[w] = v;
    __syncthreads();
    if (w == 0) {
        v = (threadIdx.x < 8) ? sh[threadIdx.x] : 0.f;
        #pragma unroll
        for (int o = 4; o; o >>= 1) v += __shfl_down_sync(0xffffffffu, v, o);
    }
    return v;  // valid in thread 0
}

// xyz coordinates computed analytically (linspace), no memory loads
__device__ __forceinline__ void coords(int v, float& xm, float& ym, float& zm) {
    int x = v % WW;
    int y = (v / WW) % HH;
    int z = v / (WW * HH);
    xm = (float)x * (1.0f / (WW - 1));
    ym = (float)y * (1.0f / (HH - 1));
    zm = (float)z * (1.0f / (DD - 1));
}

// Pass 1: per-instance moments with NO per-voxel atomics.
// lane=id design, BRANCHLESS inner loop (mask-multiply; R9 failed on BSSY/BSYNC
// from the 10-op predicated body, this version is straight-line FFMA).
__global__ void k_agg(const float* __restrict__ pred, const int* __restrict__ inst,
                      const int* __restrict__ lab) {
    __shared__ float4 sa[256];   // s0,s1,s2,idf
    __shared__ float4 sb[256];   // xm,ym,zm,0
    __shared__ float red[8];
    int t = threadIdx.x, lane = t & 31, wid = t >> 5;
    int b = blockIdx.y;
    int base = blockIdx.x * AVPB;
    const float* pb = pred + (size_t)b * NCH * DHW;
    int myid0 = lane & 15;            // 0-based id this lane accumulates
    int half = lane >> 4;

    float cnt = 0.f, sx = 0.f, sy = 0.f, sz = 0.f;
    float a0s = 0.f, a1s = 0.f, a2s = 0.f, q0 = 0.f, q1 = 0.f, q2 = 0.f;
    float bg = 0.f;

    int pbase = wid * 32 + half * 16;
    for (int rd = 0; rd < AVPB / 256; rd++) {
        int k = rd * 256 + t;
        int v = base + k;
        float s0 = pb[3 * DHW + v], s1 = pb[4 * DHW + v], s2 = pb[5 * DHW + v];
        float p6 = pb[6 * DHW + v];
        int id = inst[(size_t)b * DHW + v];
        int lb = lab[(size_t)b * DHW + v];
        if (lb == 0) { float sd = 1.f / (1.f + __expf(-p6)); bg += sd * sd; }
        float xm, ym, zm; coords(v, xm, ym, zm);
        __syncthreads();
        sa[t] = make_float4(s0, s1, s2, __int_as_float(id - 1));
        sb[t] = make_float4(xm, ym, zm, 0.f);
        __syncthreads();
        #pragma unroll
        for (int it = 0; it < 16; it++) {
            float4 A = sa[pbase + it];
            float4 C = sb[pbase + it];
            float m = (__float_as_int(A.w) == myid0) ? 1.f : 0.f;   // ISETP+SEL, no branch
            cnt += m;
            sx = fmaf(m, C.x, sx);
            sy = fmaf(m, C.y, sy);
            sz = fmaf(m, C.z, sz);
            float ax = m * A.x, ay = m * A.y, az = m * A.z;
            a0s += ax; a1s += ay; a2s += az;
            q0 = fmaf(ax, A.x, q0);        // m^2 = m, so ax*A.x = m*A.x^2
            q1 = fmaf(ay, A.y, q1);
            q2 = fmaf(az, A.z, q2);
        }
    }
    // merge half-warps (lane i += lane i+16), then flush
    cnt += __shfl_down_sync(0xffffffffu, cnt, 16);
    sx  += __shfl_down_sync(0xffffffffu, sx, 16);
    sy  += __shfl_down_sync(0xffffffffu, sy, 16);
    sz  += __shfl_down_sync(0xffffffffu, sz, 16);
    a0s += __shfl_down_sync(0xffffffffu, a0s, 16);
    a1s += __shfl_down_sync(0xffffffffu, a1s, 16);
    a2s += __shfl_down_sync(0xffffffffu, a2s, 16);
    q0  += __shfl_down_sync(0xffffffffu, q0, 16);
    q1  += __shfl_down_sync(0xffffffffu, q1, 16);
    q2  += __shfl_down_sync(0xffffffffu, q2, 16);
    if (lane < 16 && cnt != 0.f) {
        float* a = g_agg[b][myid0];
        atomicAdd(&a[0], cnt); atomicAdd(&a[1], sx);
        atomicAdd(&a[2], sy);  atomicAdd(&a[3], sz);
        atomicAdd(&a[4], a0s); atomicAdd(&a[5], a1s);
        atomicAdd(&a[6], a2s); atomicAdd(&a[7], q0);
        atomicAdd(&a[8], q1);  atomicAdd(&a[9], q2);
    }
    float bgs = blockReduceSum(bg, red);
    if (t == 0) atomicAdd(&g_misc[b][0], bgs);
}

// Pass 2: per-(b,id) derived params
__global__ void k_params() {
    int t = threadIdx.x;
    if (t >= BATCH * NIDS) return;
    int b = t >> 4, i = t & 15;
    float* a = g_agg[b][i];
    float cnt = a[0];
    float safe = fmaxf(cnt, 1.f);
    float m0 = a[4] / safe, m1 = a[5] / safe, m2 = a[6] / safe;
    float var = (a[7] - 2.f * m0 * a[4] + m0 * m0 * cnt +
                 a[8] - 2.f * m1 * a[5] + m1 * m1 * cnt +
                 a[9] - 2.f * m2 * a[6] + m2 * m2 * cnt) / (3.f * safe);
    float ex = (cnt > 0.f) ? 1.f : 0.f;
    float* p = g_params[b][i];
    p[0] = a[1] / safe; p[1] = a[2] / safe; p[2] = a[3] / safe;
    p[3] = expf(10.f * m0); p[4] = expf(10.f * m1); p[5] = expf(10.f * m2);
    p[6] = cnt; p[7] = ex;
    if (ex > 0.f) { atomicAdd(&g_misc[b][2], var); atomicAdd(&g_misc[b][3], 1.f); }
}

// Pass 3: stage spatial embeddings to smem, then lane=(voxel_pair, id) mapping so
// each RED.ADD.32 instruction writes 2 runs of 16 consecutive u32 (~4 sectors).
__global__ void k_main(const float* __restrict__ pred, const int* __restrict__ inst) {
    __shared__ float ssx[VPB], ssy[VPB], ssz[VPB];
    __shared__ int sgid[VPB];
    __shared__ float red[8];
    int t = threadIdx.x;                  // 256 threads
    int b = blockIdx.y;
    int base = blockIdx.x * VPB;
    const float* pb = pred + (size_t)b * NCH * DHW;

    int lane = t & 31, wid = t >> 5;
    int myid = lane & 15;
    const float* q = g_params[b][myid];
    float cx = q[0], cy = q[1], cz = q[2];
    float e0 = q[3], e1 = q[4], e2 = q[5];
    bool iex = (q[7] != 0.f);

    float sterm = 0.f;
    #pragma unroll
    for (int u = 0; u < 2; u++) {
        int k = u * 256 + t;
        int v = base + k;
        float xm, ym, zm; coords(v, xm, ym, zm);
        float sx = tanhf(pb[v])           + xm;
        float sy = tanhf(pb[DHW + v])     + ym;
        float sz = tanhf(pb[2 * DHW + v]) + zm;
        float seed = 1.f / (1.f + __expf(-pb[6 * DHW + v]));
        int gid = inst[(size_t)b * DHW + v] - 1;
        ssx[k] = sx; ssy[k] = sy; ssz[k] = sz; sgid[k] = gid;
        if (gid >= 0) {
            const float* qq = g_params[b][gid];
            float dx = sx - qq[0], dy = sy - qq[1], dz = sz - qq[2];
            float r = dx * dx * qq[3] + dy * dy * qq[4] + dz * dz * qq[5];
            float d = __expf(-r);
            int kn = min((int)(d * (float)NB), NB - 1);
            atomicAdd(&g_hp[b][gid][NB - 1 - kn], 1u);
            float df = seed - d; sterm += df * df;
        }
    }
    float ss = blockReduceSum(sterm, red);
    if (t == 0) atomicAdd(&g_misc[b][1], ss);
    __syncthreads();

    unsigned* hnb = &g_hn[b][0][0];
    int vb = wid * 64;
    #pragma unroll 4
    for (int it = 0; it < 32; it++) {
        int p = vb + it * 2 + (lane >> 4);
        float vx = ssx[p], vy = ssy[p], vz = ssz[p];
        int gid = sgid[p];
        float dx = vx - cx, dy = vy - cy, dz = vz - cz;
        float r = dx * dx * e0 + dy * dy * e1 + dz * dz * e2;
        float d = __expf(-r);
        int kn = min((int)(d * (float)NB), NB - 1);
        if (iex && myid != gid)
            atomicAdd(&hnb[(kn << 4) + myid], 1u);
    }
}

// Phase A: per-chunk packed (pos,neg) totals, descending-error order (j-space)
__global__ void k_chunkA() {
    int bi = blockIdx.y; int b = bi >> 4, i = bi & 15;
    int c = blockIdx.x; int t = threadIdx.x;
    const unsigned* hp = g_hp[b][i];
    unsigned long long s = 0;
    int jbase = c * CH;
    #pragma unroll
    for (int u = 0; u < CH / 256; u++) {
        int k = NB - 1 - (jbase + u * 256 + t);
        s += (((unsigned long long)hp[k]) << 32) + (unsigned long long)g_hn[b][k][i];
    }
    __shared__ unsigned long long red[8];
    #pragma unroll
    for (int o = 16; o; o >>= 1) s += __shfl_down_sync(0xffffffffu, s, o);
    int lane = t & 31, w = t >> 5;
    if (lane == 0) red[w] = s;
    __syncthreads();
    if (w == 0) {
        s = (t < 8) ? red[t] : 0ull;
        #pragma unroll
        for (int o = 4; o; o >>= 1) s += __shfl_down_sync(0xffffffffu, s, o);
        if (t == 0) g_chunk[b][i][c] = s;
    }
}

// Phase B: exclusive scan of chunk totals (per (b,id)) — 16-lane warp scan
__global__ void k_choff() {
    int bi = blockIdx.x; int b = bi >> 4, i = bi & 15;
    int t = threadIdx.x;   // 16 threads
    unsigned long long v = g_chunk[b][i][t];
    unsigned long long s = v;
    #pragma unroll
    for (int off = 1; off < 16; off <<= 1) {
        unsigned long long a = __shfl_up_sync(0xffffu, s, off);
        if (t >= off) s += a;
    }
    g_choff[b][i][t] = s - v;
}

// Phase C: evaluate Lovász loss from histogram prefix state
__global__ void k_scan() {
    int bi = blockIdx.y; int b = bi >> 4, ii = bi & 15;
    if (g_params[b][ii][7] == 0.f) return;
    float P = g_params[b][ii][6];
    int c = blockIdx.x; int t = threadIdx.x;
    const unsigned* hp = g_hp[b][ii];
    int j0 = c * CH + t * 8;
    unsigned long long vals[8]; unsigned long long ts = 0;
    #pragma unroll
    for (int u = 0; u < 8; u++) {
        int k = NB - 1 - (j0 + u);
        vals[u] = (((unsigned long long)hp[k]) << 32) + (unsigned long long)g_hn[b][k][ii];
        ts += vals[u];
    }
    __shared__ unsigned long long sh[256];
    unsigned long long orig = ts;
    sh[t] = ts; __syncthreads();
    for (int off = 1; off < 256; off <<= 1) {
        unsigned long long a = (t >= off) ? sh[t - off] : 0ull;
        __syncthreads();
        sh[t] += a;
        __syncthreads();
    }
    unsigned long long pre = sh[t] - orig + g_choff[b][ii][c];
    float acc = 0.f;
    #pragma unroll
    for (int u = 0; u < 8; u++) {
        unsigned long long cts = vals[u];
        if (cts) {
            float S0 = (float)(unsigned)(pre >> 32);
            float i0 = S0 + (float)(unsigned)pre;
            float p = (float)(unsigned)(cts >> 32), n = (float)(unsigned)cts;
            float S1 = S0 + p, i1 = i0 + p + n;
            float J0 = 1.f - (P - S0) / (P + i0 - S0);
            float J1 = 1.f - (P - S1) / (P + i1 - S1);
            int k = NB - 1 - (j0 + u);
            float e = ((float)k + 0.5f) * BUCKW;
            acc += e * (J1 - J0);
        }
        pre += cts;
    }
    __shared__ float redf[8];
    float a2 = blockReduceSum(acc, redf);
    if (t == 0 && a2 != 0.f) atomicAdd(&g_instl[b], a2);
}

__global__ void k_final(float* out) {
    float li = 0.f, lv = 0.f, ls = 0.f;
    for (int b = 0; b < BATCH; b++) {
        float denom = fmaxf(g_misc[b][3], 1.f);
        li += g_instl[b] / denom;
        lv += g_misc[b][2] / denom;
        ls += (g_misc[b][1] + g_misc[b][0]) / (float)DHW;
    }
    li *= 1.0f / BATCH;
    lv *= 10.0f / BATCH;
    ls *= 1.0f / BATCH;
    out[0] = li; out[1] = lv; out[2] = ls; out[3] = li + lv + ls;
}

extern "C" void kernel_launch(void* const* d_in, const int* in_sizes, int n_in,
                              void* d_out, int out_size) {
    const float* pred = (const float*)d_in[0];
    const int* inst   = (const int*)d_in[1];
    const int* lab    = (const int*)d_in[2];
    // d_in[3] = center_images (unused by reference), d_in[4] = xyzm (computed analytically)
    float* out = (float*)d_out;

    void *php, *phn, *pa, *pm, *pi;
    cudaGetSymbolAddress(&php, g_hp);
    cudaGetSymbolAddress(&phn, g_hn);
    cudaGetSymbolAddress(&pa, g_agg);
    cudaGetSymbolAddress(&pm, g_misc);
    cudaGetSymbolAddress(&pi, g_instl);
    cudaMemsetAsync(php, 0, sizeof(g_hp));
    cudaMemsetAsync(phn, 0, sizeof(g_hn));
    cudaMemsetAsync(pa, 0, sizeof(g_agg));
    cudaMemsetAsync(pm, 0, sizeof(g_misc));
    cudaMemsetAsync(pi, 0, sizeof(g_instl));

    k_agg<<<dim3(DHW / AVPB, BATCH), 256>>>(pred, inst, lab);
    k_params<<<1, 64>>>();
    k_main<<<dim3(DHW / VPB, BATCH), 256>>>(pred, inst);
    k_chunkA<<<dim3(NCHUNK, BATCH * NIDS), 256>>>();
    k_choff<<<BATCH * NIDS, 16>>>();
    k_scan<<<dim3(NCHUNK, BATCH * NIDS), 256>>>();
    k_final<<<1, 1>>>(out);
}

// round 12
// speedup vs baseline: 1.8316x; 1.8316x over previous
#include <cuda_runtime.h>

#define BATCH 4
#define DD 32
#define HH 192
#define WW 192
#define DHW 1179648
#define NCH 7
#define NIDS 16
#define NB 32768                     // bucketing error <= 1/NB (provable)
#define CH 2048
#define NCHUNK (NB / CH)             // 16
#define BUCKW (2.0f / (float)NB)
#define VPB 512                      // voxels per k_main block

// Scratch (static device globals; no allocation anywhere)
__device__ unsigned g_hp[BATCH][NIDS][NB];   // pos hist, id-major (gt is scattered anyway)
__device__ unsigned g_hn[BATCH][NB][NIDS];   // neg hist, id-MINOR: 16 ids contiguous per bucket
__device__ unsigned long long g_chunk[BATCH][NIDS][NCHUNK];
__device__ unsigned long long g_choff[BATCH][NIDS][NCHUNK];
__device__ float g_agg[BATCH][NIDS][8];    // cnt, sx,sy,sz, s0,s1,s2, q(=Σσ0²+σ1²+σ2²)
__device__ float g_params[BATCH][NIDS][8]; // cx,cy,cz, e0,e1,e2, P, exists
__device__ float g_misc[BATCH][4];         // bg_seed, seed_l, var_sum, denom
__device__ float g_instl[BATCH];

__device__ __forceinline__ float blockReduceSum(float v, float* sh) {
    #pragma unroll
    for (int o = 16; o; o >>= 1) v += __shfl_down_sync(0xffffffffu, v, o);
    int lane = threadIdx.x & 31, w = threadIdx.x >> 5;
    if (lane == 0) sh[w] = v;
    __syncthreads();
    if (w == 0) {
        v = (threadIdx.x < 8) ? sh[threadIdx.x] : 0.f;
        #pragma unroll
        for (int o = 4; o; o >>= 1) v += __shfl_down_sync(0xffffffffu, v, o);
    }
    return v;  // valid in thread 0
}

// xyz coordinates computed analytically (linspace), no memory loads
__device__ __forceinline__ void coords(int v, float& xm, float& ym, float& zm) {
    int x = v % WW;
    int y = (v / WW) % HH;
    int z = v / (WW * HH);
    xm = (float)x * (1.0f / (WW - 1));
    ym = (float)y * (1.0f / (HH - 1));
    zm = (float)z * (1.0f / (DD - 1));
}

// Pass 1: per-instance moments via smem atomics (proven R7 design),
// with q0,q1,q2 merged into one accumulator (exact: var only needs their sum).
__global__ void k_agg(const float* __restrict__ pred, const int* __restrict__ inst,
                      const int* __restrict__ lab) {
    __shared__ float sh[NIDS * 8];
    __shared__ float red[8];
    int t = threadIdx.x;
    if (t < NIDS * 8) sh[t] = 0.f;
    __syncthreads();
    int b = blockIdx.y;
    int v = blockIdx.x * 256 + t;
    const float* pb = pred + (size_t)b * NCH * DHW;
    float s0 = pb[3 * DHW + v], s1 = pb[4 * DHW + v], s2 = pb[5 * DHW + v];
    float p6 = pb[6 * DHW + v];
    int id = inst[(size_t)b * DHW + v];
    int lb = lab[(size_t)b * DHW + v];
    float bg = 0.f;
    if (lb == 0) { float sd = 1.f / (1.f + __expf(-p6)); bg = sd * sd; }
    if (id > 0) {
        float xm, ym, zm; coords(v, xm, ym, zm);
        int s = (id - 1) * 8;
        float q = s0 * s0 + s1 * s1 + s2 * s2;
        atomicAdd(&sh[s + 0], 1.f);
        atomicAdd(&sh[s + 1], xm);
        atomicAdd(&sh[s + 2], ym);
        atomicAdd(&sh[s + 3], zm);
        atomicAdd(&sh[s + 4], s0);
        atomicAdd(&sh[s + 5], s1);
        atomicAdd(&sh[s + 6], s2);
        atomicAdd(&sh[s + 7], q);
    }
    float bgs = blockReduceSum(bg, red);
    if (t == 0) atomicAdd(&g_misc[b][0], bgs);
    __syncthreads();
    if (t < NIDS * 8) atomicAdd(&((float*)g_agg[b])[t], sh[t]);
}

// Pass 2: per-(b,id) derived params
__global__ void k_params() {
    int t = threadIdx.x;
    if (t >= BATCH * NIDS) return;
    int b = t >> 4, i = t & 15;
    float* a = g_agg[b][i];
    float cnt = a[0];
    float safe = fmaxf(cnt, 1.f);
    float m0 = a[4] / safe, m1 = a[5] / safe, m2 = a[6] / safe;
    float var = (a[7]
                 - 2.f * (m0 * a[4] + m1 * a[5] + m2 * a[6])
                 + (m0 * m0 + m1 * m1 + m2 * m2) * cnt) / (3.f * safe);
    float ex = (cnt > 0.f) ? 1.f : 0.f;
    float* p = g_params[b][i];
    p[0] = a[1] / safe; p[1] = a[2] / safe; p[2] = a[3] / safe;
    p[3] = expf(10.f * m0); p[4] = expf(10.f * m1); p[5] = expf(10.f * m2);
    p[6] = cnt; p[7] = ex;
    if (ex > 0.f) { atomicAdd(&g_misc[b][2], var); atomicAdd(&g_misc[b][3], 1.f); }
}

// Pass 3: stage spatial embeddings to smem, then lane=(voxel_pair, id) mapping so
// each RED.ADD.32 instruction writes 2 runs of 16 consecutive u32 (~4 sectors).
__global__ void k_main(const float* __restrict__ pred, const int* __restrict__ inst) {
    __shared__ float ssx[VPB], ssy[VPB], ssz[VPB];
    __shared__ int sgid[VPB];
    __shared__ float red[8];
    int t = threadIdx.x;                  // 256 threads
    int b = blockIdx.y;
    int base = blockIdx.x * VPB;
    const float* pb = pred + (size_t)b * NCH * DHW;

    int lane = t & 31, wid = t >> 5;
    int myid = lane & 15;
    const float* q = g_params[b][myid];
    float cx = q[0], cy = q[1], cz = q[2];
    float e0 = q[3], e1 = q[4], e2 = q[5];
    bool iex = (q[7] != 0.f);

    float sterm = 0.f;
    #pragma unroll
    for (int u = 0; u < 2; u++) {
        int k = u * 256 + t;
        int v = base + k;
        float xm, ym, zm; coords(v, xm, ym, zm);
        float sx = tanhf(pb[v])           + xm;
        float sy = tanhf(pb[DHW + v])     + ym;
        float sz = tanhf(pb[2 * DHW + v]) + zm;
        float seed = 1.f / (1.f + __expf(-pb[6 * DHW + v]));
        int gid = inst[(size_t)b * DHW + v] - 1;
        ssx[k] = sx; ssy[k] = sy; ssz[k] = sz; sgid[k] = gid;
        if (gid >= 0) {
            const float* qq = g_params[b][gid];
            float dx = sx - qq[0], dy = sy - qq[1], dz = sz - qq[2];
            float r = dx * dx * qq[3] + dy * dy * qq[4] + dz * dz * qq[5];
            float d = __expf(-r);
            int kn = min((int)(d * (float)NB), NB - 1);
            atomicAdd(&g_hp[b][gid][NB - 1 - kn], 1u);
            float df = seed - d; sterm += df * df;
        }
    }
    float ss = blockReduceSum(sterm, red);
    if (t == 0) atomicAdd(&g_misc[b][1], ss);
    __syncthreads();

    unsigned* hnb = &g_hn[b][0][0];
    int vb = wid * 64;
    #pragma unroll 4
    for (int it = 0; it < 32; it++) {
        int p = vb + it * 2 + (lane >> 4);
        float vx = ssx[p], vy = ssy[p], vz = ssz[p];
        int gid = sgid[p];
        float dx = vx - cx, dy = vy - cy, dz = vz - cz;
        float r = dx * dx * e0 + dy * dy * e1 + dz * dz * e2;
        float d = __expf(-r);
        int kn = min((int)(d * (float)NB), NB - 1);
        if (iex && myid != gid)
            atomicAdd(&hnb[(kn << 4) + myid], 1u);
    }
}

// Phase A: per-chunk packed (pos,neg) totals, descending-error order (j-space)
__global__ void k_chunkA() {
    int bi = blockIdx.y; int b = bi >> 4, i = bi & 15;
    int c = blockIdx.x; int t = threadIdx.x;
    const unsigned* hp = g_hp[b][i];
    unsigned long long s = 0;
    int jbase = c * CH;
    #pragma unroll
    for (int u = 0; u < CH / 256; u++) {
        int k = NB - 1 - (jbase + u * 256 + t);
        s += (((unsigned long long)hp[k]) << 32) + (unsigned long long)g_hn[b][k][i];
    }
    __shared__ unsigned long long red[8];
    #pragma unroll
    for (int o = 16; o; o >>= 1) s += __shfl_down_sync(0xffffffffu, s, o);
    int lane = t & 31, w = t >> 5;
    if (lane == 0) red[w] = s;
    __syncthreads();
    if (w == 0) {
        s = (t < 8) ? red[t] : 0ull;
        #pragma unroll
        for (int o = 4; o; o >>= 1) s += __shfl_down_sync(0xffffffffu, s, o);
        if (t == 0) g_chunk[b][i][c] = s;
    }
}

// Phase B: exclusive scan of chunk totals (per (b,id)) — 16-lane warp scan
__global__ void k_choff() {
    int bi = blockIdx.x; int b = bi >> 4, i = bi & 15;
    int t = threadIdx.x;   // 16 threads
    unsigned long long v = g_chunk[b][i][t];
    unsigned long long s = v;
    #pragma unroll
    for (int off = 1; off < 16; off <<= 1) {
        unsigned long long a = __shfl_up_sync(0xffffu, s, off);
        if (t >= off) s += a;
    }
    g_choff[b][i][t] = s - v;
}

// Phase C: evaluate Lovász loss from histogram prefix state
__global__ void k_scan() {
    int bi = blockIdx.y; int b = bi >> 4, ii = bi & 15;
    if (g_params[b][ii][7] == 0.f) return;
    float P = g_params[b][ii][6];
    int c = blockIdx.x; int t = threadIdx.x;
    const unsigned* hp = g_hp[b][ii];
    int j0 = c * CH + t * 8;
    unsigned long long vals[8]; unsigned long long ts = 0;
    #pragma unroll
    for (int u = 0; u < 8; u++) {
        int k = NB - 1 - (j0 + u);
        vals[u] = (((unsigned long long)hp[k]) << 32) + (unsigned long long)g_hn[b][k][ii];
        ts += vals[u];
    }
    __shared__ unsigned long long sh[256];
    unsigned long long orig = ts;
    sh[t] = ts; __syncthreads();
    for (int off = 1; off < 256; off <<= 1) {
        unsigned long long a = (t >= off) ? sh[t - off] : 0ull;
        __syncthreads();
        sh[t] += a;
        __syncthreads();
    }
    unsigned long long pre = sh[t] - orig + g_choff[b][ii][c];
    float acc = 0.f;
    #pragma unroll
    for (int u = 0; u < 8; u++) {
        unsigned long long cts = vals[u];
        if (cts) {
            float S0 = (float)(unsigned)(pre >> 32);
            float i0 = S0 + (float)(unsigned)pre;
            float p = (float)(unsigned)(cts >> 32), n = (float)(unsigned)cts;
            float S1 = S0 + p, i1 = i0 + p + n;
            float J0 = 1.f - (P - S0) / (P + i0 - S0);
            float J1 = 1.f - (P - S1) / (P + i1 - S1);
            int k = NB - 1 - (j0 + u);
            float e = ((float)k + 0.5f) * BUCKW;
            acc += e * (J1 - J0);
        }
        pre += cts;
    }
    __shared__ float redf[8];
    float a2 = blockReduceSum(acc, redf);
    if (t == 0 && a2 != 0.f) atomicAdd(&g_instl[b], a2);
}

__global__ void k_final(float* out) {
    float li = 0.f, lv = 0.f, ls = 0.f;
    for (int b = 0; b < BATCH; b++) {
        float denom = fmaxf(g_misc[b][3], 1.f);
        li += g_instl[b] / denom;
        lv += g_misc[b][2] / denom;
        ls += (g_misc[b][1] + g_misc[b][0]) / (float)DHW;
    }
    li *= 1.0f / BATCH;
    lv *= 10.0f / BATCH;
    ls *= 1.0f / BATCH;
    out[0] = li; out[1] = lv; out[2] = ls; out[3] = li + lv + ls;
}

extern "C" void kernel_launch(void* const* d_in, const int* in_sizes, int n_in,
                              void* d_out, int out_size) {
    const float* pred = (const float*)d_in[0];
    const int* inst   = (const int*)d_in[1];
    const int* lab    = (const int*)d_in[2];
    // d_in[3] = center_images (unused by reference), d_in[4] = xyzm (computed analytically)
    float* out = (float*)d_out;

    void *php, *phn, *pa, *pm, *pi;
    cudaGetSymbolAddress(&php, g_hp);
    cudaGetSymbolAddress(&phn, g_hn);
    cudaGetSymbolAddress(&pa, g_agg);
    cudaGetSymbolAddress(&pm, g_misc);
    cudaGetSymbolAddress(&pi, g_instl);
    cudaMemsetAsync(php, 0, sizeof(g_hp));
    cudaMemsetAsync(phn, 0, sizeof(g_hn));
    cudaMemsetAsync(pa, 0, sizeof(g_agg));
    cudaMemsetAsync(pm, 0, sizeof(g_misc));
    cudaMemsetAsync(pi, 0, sizeof(g_instl));

    k_agg<<<dim3(DHW / 256, BATCH), 256>>>(pred, inst, lab);
    k_params<<<1, 64>>>();
    k_main<<<dim3(DHW / VPB, BATCH), 256>>>(pred, inst);
    k_chunkA<<<dim3(NCHUNK, BATCH * NIDS), 256>>>();
    k_choff<<<BATCH * NIDS, 16>>>();
    k_scan<<<dim3(NCHUNK, BATCH * NIDS), 256>>>();
    k_final<<<1, 1>>>(out);
}

// round 13
// speedup vs baseline: 2.3020x; 1.2568x over previous
#include <cuda_runtime.h>

#define BATCH 4
#define DD 32
#define HH 192
#define WW 192
#define DHW 1179648
#define NCH 7
#define NIDS 16
#define NB 32768                     // bucketing error <= 1/NB (provable)
#define CH 2048
#define NCHUNK (NB / CH)             // 16
#define BUCKW (2.0f / (float)NB)
#define VPB 512                      // voxels per k_main block
#define ASTR 9                       // per-id smem stride: 9*i mod 32 distinct for i<16
                                     // -> zero cross-id bank conflicts on smem atomics

// Scratch (static device globals; no allocation anywhere)
__device__ unsigned g_hp[BATCH][NIDS][NB];   // pos hist, id-major (gt is scattered anyway)
__device__ unsigned g_hn[BATCH][NB][NIDS];   // neg hist, id-MINOR: 16 ids contiguous per bucket
__device__ unsigned long long g_chunk[BATCH][NIDS][NCHUNK];
__device__ unsigned long long g_choff[BATCH][NIDS][NCHUNK];
__device__ float g_agg[BATCH][NIDS][8];    // cnt, sx,sy,sz, s0,s1,s2, q(=Σσ0²+σ1²+σ2²)
__device__ float g_params[BATCH][NIDS][8]; // cx,cy,cz, e0,e1,e2, P, exists
__device__ float g_misc[BATCH][4];         // bg_seed, seed_l, var_sum, denom
__device__ float g_instl[BATCH];

__device__ __forceinline__ float blockReduceSum(float v, float* sh) {
    #pragma unroll
    for (int o = 16; o; o >>= 1) v += __shfl_down_sync(0xffffffffu, v, o);
    int lane = threadIdx.x & 31, w = threadIdx.x >> 5;
    if (lane == 0) sh[w] = v;
    __syncthreads();
    if (w == 0) {
        v = (threadIdx.x < 8) ? sh[threadIdx.x] : 0.f;
        #pragma unroll
        for (int o = 4; o; o >>= 1) v += __shfl_down_sync(0xffffffffu, v, o);
    }
    return v;  // valid in thread 0
}

// xyz coordinates computed analytically (linspace), no memory loads
__device__ __forceinline__ void coords(int v, float& xm, float& ym, float& zm) {
    int x = v % WW;
    int y = (v / WW) % HH;
    int z = v / (WW * HH);
    xm = (float)x * (1.0f / (WW - 1));
    ym = (float)y * (1.0f / (HH - 1));
    zm = (float)z * (1.0f / (DD - 1));
}

// Pass 1: per-instance moments via smem atomics, 8 atomics/voxel,
// stride-9 layout for conflict-free banks across ids.
__global__ void k_agg(const float* __restrict__ pred, const int* __restrict__ inst,
                      const int* __restrict__ lab) {
    __shared__ float sh[NIDS * ASTR];
    __shared__ float red[8];
    int t = threadIdx.x;
    if (t < NIDS * ASTR) sh[t] = 0.f;
    __syncthreads();
    int b = blockIdx.y;
    int v = blockIdx.x * 256 + t;
    const float* pb = pred + (size_t)b * NCH * DHW;
    float s0 = pb[3 * DHW + v], s1 = pb[4 * DHW + v], s2 = pb[5 * DHW + v];
    float p6 = pb[6 * DHW + v];
    int id = inst[(size_t)b * DHW + v];
    int lb = lab[(size_t)b * DHW + v];
    float bg = 0.f;
    if (lb == 0) { float sd = 1.f / (1.f + __expf(-p6)); bg = sd * sd; }
    if (id > 0) {
        float xm, ym, zm; coords(v, xm, ym, zm);
        int s = (id - 1) * ASTR;
        float q = s0 * s0 + s1 * s1 + s2 * s2;
        atomicAdd(&sh[s + 0], 1.f);
        atomicAdd(&sh[s + 1], xm);
        atomicAdd(&sh[s + 2], ym);
        atomicAdd(&sh[s + 3], zm);
        atomicAdd(&sh[s + 4], s0);
        atomicAdd(&sh[s + 5], s1);
        atomicAdd(&sh[s + 6], s2);
        atomicAdd(&sh[s + 7], q);
    }
    float bgs = blockReduceSum(bg, red);
    if (t == 0) atomicAdd(&g_misc[b][0], bgs);
    __syncthreads();
    if (t < NIDS * 8) {
        int i = t >> 3, j = t & 7;
        float val = sh[i * ASTR + j];
        if (val != 0.f) atomicAdd(&g_agg[b][i][j], val);
    }
}

// Pass 2: per-(b,id) derived params
__global__ void k_params() {
    int t = threadIdx.x;
    if (t >= BATCH * NIDS) return;
    int b = t >> 4, i = t & 15;
    float* a = g_agg[b][i];
    float cnt = a[0];
    float safe = fmaxf(cnt, 1.f);
    float m0 = a[4] / safe, m1 = a[5] / safe, m2 = a[6] / safe;
    float var = (a[7]
                 - 2.f * (m0 * a[4] + m1 * a[5] + m2 * a[6])
                 + (m0 * m0 + m1 * m1 + m2 * m2) * cnt) / (3.f * safe);
    float ex = (cnt > 0.f) ? 1.f : 0.f;
    float* p = g_params[b][i];
    p[0] = a[1] / safe; p[1] = a[2] / safe; p[2] = a[3] / safe;
    p[3] = expf(10.f * m0); p[4] = expf(10.f * m1); p[5] = expf(10.f * m2);
    p[6] = cnt; p[7] = ex;
    if (ex > 0.f) { atomicAdd(&g_misc[b][2], var); atomicAdd(&g_misc[b][3], 1.f); }
}

// Pass 3: stage spatial embeddings to smem, then lane=(voxel_pair, id) mapping so
// each RED.ADD.32 instruction writes 2 runs of 16 consecutive u32 (~4 sectors).
__global__ void k_main(const float* __restrict__ pred, const int* __restrict__ inst) {
    __shared__ float ssx[VPB], ssy[VPB], ssz[VPB];
    __shared__ int sgid[VPB];
    __shared__ float red[8];
    int t = threadIdx.x;                  // 256 threads
    int b = blockIdx.y;
    int base = blockIdx.x * VPB;
    const float* pb = pred + (size_t)b * NCH * DHW;

    int lane = t & 31, wid = t >> 5;
    int myid = lane & 15;
    const float* q = g_params[b][myid];
    float cx = q[0], cy = q[1], cz = q[2];
    float e0 = q[3], e1 = q[4], e2 = q[5];
    bool iex = (q[7] != 0.f);

    float sterm = 0.f;
    #pragma unroll
    for (int u = 0; u < 2; u++) {
        int k = u * 256 + t;
        int v = base + k;
        float xm, ym, zm; coords(v, xm, ym, zm);
        float sx = tanhf(pb[v])           + xm;
        float sy = tanhf(pb[DHW + v])     + ym;
        float sz = tanhf(pb[2 * DHW + v]) + zm;
        float seed = 1.f / (1.f + __expf(-pb[6 * DHW + v]));
        int gid = inst[(size_t)b * DHW + v] - 1;
        ssx[k] = sx; ssy[k] = sy; ssz[k] = sz; sgid[k] = gid;
        if (gid >= 0) {
            const float* qq = g_params[b][gid];
            float dx = sx - qq[0], dy = sy - qq[1], dz = sz - qq[2];
            float r = dx * dx * qq[3] + dy * dy * qq[4] + dz * dz * qq[5];
            float d = __expf(-r);
            int kn = min((int)(d * (float)NB), NB - 1);
            atomicAdd(&g_hp[b][gid][NB - 1 - kn], 1u);
            float df = seed - d; sterm += df * df;
        }
    }
    float ss = blockReduceSum(sterm, red);
    if (t == 0) atomicAdd(&g_misc[b][1], ss);
    __syncthreads();

    unsigned* hnb = &g_hn[b][0][0];
    int vb = wid * 64;
    #pragma unroll 4
    for (int it = 0; it < 32; it++) {
        int p = vb + it * 2 + (lane >> 4);
        float vx = ssx[p], vy = ssy[p], vz = ssz[p];
        int gid = sgid[p];
        float dx = vx - cx, dy = vy - cy, dz = vz - cz;
        float r = dx * dx * e0 + dy * dy * e1 + dz * dz * e2;
        float d = __expf(-r);
        int kn = min((int)(d * (float)NB), NB - 1);
        if (iex && myid != gid)
            atomicAdd(&hnb[(kn << 4) + myid], 1u);
    }
}

// Phase A: per-chunk packed (pos,neg) totals, descending-error order (j-space)
__global__ void k_chunkA() {
    int bi = blockIdx.y; int b = bi >> 4, i = bi & 15;
    int c = blockIdx.x; int t = threadIdx.x;
    const unsigned* hp = g_hp[b][i];
    unsigned long long s = 0;
    int jbase = c * CH;
    #pragma unroll
    for (int u = 0; u < CH / 256; u++) {
        int k = NB - 1 - (jbase + u * 256 + t);
        s += (((unsigned long long)hp[k]) << 32) + (unsigned long long)g_hn[b][k][i];
    }
    __shared__ unsigned long long red[8];
    #pragma unroll
    for (int o = 16; o; o >>= 1) s += __shfl_down_sync(0xffffffffu, s, o);
    int lane = t & 31, w = t >> 5;
    if (lane == 0) red[w] = s;
    __syncthreads();
    if (w == 0) {
        s = (t < 8) ? red[t] : 0ull;
        #pragma unroll
        for (int o = 4; o; o >>= 1) s += __shfl_down_sync(0xffffffffu, s, o);
        if (t == 0) g_chunk[b][i][c] = s;
    }
}

// Phase B: exclusive scan of chunk totals (per (b,id)) — 16-lane warp scan
__global__ void k_choff() {
    int bi = blockIdx.x; int b = bi >> 4, i = bi & 15;
    int t = threadIdx.x;   // 16 threads
    unsigned long long v = g_chunk[b][i][t];
    unsigned long long s = v;
    #pragma unroll
    for (int off = 1; off < 16; off <<= 1) {
        unsigned long long a = __shfl_up_sync(0xffffu, s, off);
        if (t >= off) s += a;
    }
    g_choff[b][i][t] = s - v;
}

// Phase C: evaluate Lovász loss from histogram prefix state
__global__ void k_scan() {
    int bi = blockIdx.y; int b = bi >> 4, ii = bi & 15;
    if (g_params[b][ii][7] == 0.f) return;
    float P = g_params[b][ii][6];
    int c = blockIdx.x; int t = threadIdx.x;
    const unsigned* hp = g_hp[b][ii];
    int j0 = c * CH + t * 8;
    unsigned long long vals[8]; unsigned long long ts = 0;
    #pragma unroll
    for (int u = 0; u < 8; u++) {
        int k = NB - 1 - (j0 + u);
        vals[u] = (((unsigned long long)hp[k]) << 32) + (unsigned long long)g_hn[b][k][ii];
        ts += vals[u];
    }
    __shared__ unsigned long long sh[256];
    unsigned long long orig = ts;
    sh[t] = ts; __syncthreads();
    for (int off = 1; off < 256; off <<= 1) {
        unsigned long long a = (t >= off) ? sh[t - off] : 0ull;
        __syncthreads();
        sh[t] += a;
        __syncthreads();
    }
    unsigned long long pre = sh[t] - orig + g_choff[b][ii][c];
    float acc = 0.f;
    #pragma unroll
    for (int u = 0; u < 8; u++) {
        unsigned long long cts = vals[u];
        if (cts) {
            float S0 = (float)(unsigned)(pre >> 32);
            float i0 = S0 + (float)(unsigned)pre;
            float p = (float)(unsigned)(cts >> 32), n = (float)(unsigned)cts;
            float S1 = S0 + p, i1 = i0 + p + n;
            float J0 = 1.f - (P - S0) / (P + i0 - S0);
            float J1 = 1.f - (P - S1) / (P + i1 - S1);
            int k = NB - 1 - (j0 + u);
            float e = ((float)k + 0.5f) * BUCKW;
            acc += e * (J1 - J0);
        }
        pre += cts;
    }
    __shared__ float redf[8];
    float a2 = blockReduceSum(acc, redf);
    if (t == 0 && a2 != 0.f) atomicAdd(&g_instl[b], a2);
}

__global__ void k_final(float* out) {
    float li = 0.f, lv = 0.f, ls = 0.f;
    for (int b = 0; b < BATCH; b++) {
        float denom = fmaxf(g_misc[b][3], 1.f);
        li += g_instl[b] / denom;
        lv += g_misc[b][2] / denom;
        ls += (g_misc[b][1] + g_misc[b][0]) / (float)DHW;
    }
    li *= 1.0f / BATCH;
    lv *= 10.0f / BATCH;
    ls *= 1.0f / BATCH;
    out[0] = li; out[1] = lv; out[2] = ls; out[3] = li + lv + ls;
}

extern "C" void kernel_launch(void* const* d_in, const int* in_sizes, int n_in,
                              void* d_out, int out_size) {
    const float* pred = (const float*)d_in[0];
    const int* inst   = (const int*)d_in[1];
    const int* lab    = (const int*)d_in[2];
    // d_in[3] = center_images (unused by reference), d_in[4] = xyzm (computed analytically)
    float* out = (float*)d_out;

    void *php, *phn, *pa, *pm, *pi;
    cudaGetSymbolAddress(&php, g_hp);
    cudaGetSymbolAddress(&phn, g_hn);
    cudaGetSymbolAddress(&pa, g_agg);
    cudaGetSymbolAddress(&pm, g_misc);
    cudaGetSymbolAddress(&pi, g_instl);
    cudaMemsetAsync(php, 0, sizeof(g_hp));
    cudaMemsetAsync(phn, 0, sizeof(g_hn));
    cudaMemsetAsync(pa, 0, sizeof(g_agg));
    cudaMemsetAsync(pm, 0, sizeof(g_misc));
    cudaMemsetAsync(pi, 0, sizeof(g_instl));

    k_agg<<<dim3(DHW / 256, BATCH), 256>>>(pred, inst, lab);
    k_params<<<1, 64>>>();
    k_main<<<dim3(DHW / VPB, BATCH), 256>>>(pred, inst);
    k_chunkA<<<dim3(NCHUNK, BATCH * NIDS), 256>>>();
    k_choff<<<BATCH * NIDS, 16>>>();
    k_scan<<<dim3(NCHUNK, BATCH * NIDS), 256>>>();
    k_final<<<1, 1>>>(out);
}